// round 14
// baseline (speedup 1.0000x reference)
#include <cuda_runtime.h>
#include <cuda_fp16.h>

// Problem constants
#define CNUM  19
#define NB    32            // error bins over [0,1]
#define STRIDE 80           // words/class: nonfg bin b at [b] (b<=32); fg bin b at [40+b]
#define NREP  16            // histogram replicas
#define HW    262144        // 512*512
#define PTOT  1048576       // 4*512*512
#define GRID  (PTOT / 512)  // 2048 blocks, 256 threads, 2 pixels/thread

// [replica][class][80]; zero-init at load; fused epilogue re-zeroes.
__device__ __align__(16) unsigned g_hist[NREP * CNUM * STRIDE];
__device__ unsigned g_done;          // completion counter (wraps to 0 each run)

__device__ __forceinline__ float rcpf(float x) { float r; asm("rcp.approx.ftz.f32 %0,%1;":"=f"(r):"f"(x)); return r; }

// ---------------------------------------------------------------------------
// Single fused kernel: per-pixel softmax + warp-aggregated error histogram;
// the last block to finish merges replicas, computes all 19 class losses
// (one warp per class, shfl suffix scans) and writes the scalar output.
// ---------------------------------------------------------------------------
__global__ void __launch_bounds__(256) lovasz_kernel(
    const float* __restrict__ logits, const int* __restrict__ gt,
    float* __restrict__ out)
{
    const int tid  = threadIdx.x;
    const int lane = tid & 31;
    const int wid  = tid >> 5;

    // ---------------- histogram phase: 2 pixels per thread ----------------
    int pp = blockIdx.x * blockDim.x + tid;       // pixel-pair index
    int p0 = pp << 1;
    int b  = p0 >> 18;
    int hw = p0 & (HW - 1);                       // even; hw+1 same batch row
    const float* base = logits + (size_t)b * CNUM * HW + hw;

    int2 lab = *reinterpret_cast<const int2*>(gt + p0);
    bool v0 = ((unsigned)lab.x < (unsigned)CNUM);
    bool v1 = ((unsigned)lab.y < (unsigned)CNUM);
    int lab0 = v0 ? lab.x : -1;
    int lab1 = v1 ? lab.y : -1;

    const float L2E = 1.4426950408889634f;

    __half2 e2[CNUM];                              // lo=pixel0, hi=pixel1
    float S0 = 0.f, S1 = 0.f;
#pragma unroll
    for (int c = 0; c < CNUM; c++) {
        float2 x = *reinterpret_cast<const float2*>(base + (size_t)c * HW);
        __half2 y = __floats2half2_rn(x.x * L2E, x.y * L2E);
        __half2 ee = h2exp2(y);                    // 2 exps (one per pixel)
        e2[c] = ee;
        float2 ef = __half22float2(ee);
        S0 += ef.x; S1 += ef.y;
    }

    float rsn0 = rcpf(S0) * (float)NB;
    float rsn1 = rcpf(S1) * (float)NB;

    unsigned* baseH = g_hist + (size_t)(blockIdx.x & (NREP - 1)) * (CNUM * STRIDE);

#pragma unroll
    for (int c = 0; c < CNUM; c++) {
        float2 ef = __half22float2(e2[c]);
        // pixel 0
        {
            float pcN = ef.x * rsn0;
            int ig = (int)((float)NB - pcN); ig = ig < 0 ? 0 : ig;
            unsigned idx = (c == lab0) ? (40u + (unsigned)ig) : (unsigned)pcN;
            bool emit = v0 && (idx != 0u);
            unsigned off = emit ? ((unsigned)c * STRIDE + idx)
                                : (0x40000000u + (unsigned)c);
            unsigned mask = __match_any_sync(0xFFFFFFFFu, off);
            bool leader = ((unsigned)lane == (unsigned)(__ffs(mask) - 1));
            if (emit && leader) atomicAdd(baseH + off, __popc(mask));
        }
        // pixel 1
        {
            float pcN = ef.y * rsn1;
            int ig = (int)((float)NB - pcN); ig = ig < 0 ? 0 : ig;
            unsigned idx = (c == lab1) ? (40u + (unsigned)ig) : (unsigned)pcN;
            bool emit = v1 && (idx != 0u);
            unsigned off = emit ? ((unsigned)c * STRIDE + idx)
                                : (0x40000000u + (unsigned)c);
            unsigned mask = __match_any_sync(0xFFFFFFFFu, off);
            bool leader = ((unsigned)lane == (unsigned)(__ffs(mask) - 1));
            if (emit && leader) atomicAdd(baseH + off, __popc(mask));
        }
    }

    // ---------------- completion detection ----------------
    __shared__ bool amLast;
    __syncthreads();                                // all block REDs issued
    if (tid == 0) {
        __threadfence();                            // REDs visible device-wide
        unsigned prev = atomicInc(&g_done, GRID - 1);   // wraps to 0 at GRID
        amLast = (prev == GRID - 1);
    }
    __syncthreads();
    if (!amLast) return;

    // ---------------- fused epilogue (last block only) ----------------
    __threadfence();                                // acquire all blocks' REDs

    __shared__ unsigned mg[CNUM * STRIDE];          // 1520 words
    __shared__ float    lossc[CNUM];
    __shared__ unsigned gtsc[CNUM];

    for (int i = tid; i < CNUM * STRIDE; i += 256) {
        unsigned sum = 0;
#pragma unroll
        for (int r = 0; r < NREP; r++) {
            size_t idx = (size_t)r * (CNUM * STRIDE) + i;
            sum += g_hist[idx];
            g_hist[idx] = 0u;                       // restore zero-invariant
        }
        mg[i] = sum;
    }
    __syncthreads();

    // one warp per class (8 warps cover 19 classes in 3 rounds)
    for (int c = wid; c < CNUM; c += 8) {
        const unsigned* row = mg + c * STRIDE;
        unsigned u = row[lane];                     // nonfg err bin t=lane
        unsigned f = row[40 + lane];                // fg err bin t=lane
        unsigned u32 = row[32];                     // tail bin t=32
        unsigned f32 = row[72];

        // inclusive suffix scan over lanes (t = lane .. 31)
#pragma unroll
        for (int off = 1; off < 32; off <<= 1) {
            unsigned un = __shfl_down_sync(0xFFFFFFFFu, u, off);
            unsigned fn = __shfl_down_sync(0xFFFFFFFFu, f, off);
            if (lane + off < 32) { u += un; f += fn; }
        }
        u += u32; f += f32;                         // include bin 32

        unsigned gts = __shfl_sync(0xFFFFFFFFu, f, 0);  // suffix from t=0

        float J = 0.f;
        if (lane >= 1 && gts > 0)
            J = 1.f - __fdividef((float)(gts - f), (float)(gts + u));
        // warp sum of J over lanes 1..31
#pragma unroll
        for (int off = 16; off > 0; off >>= 1)
            J += __shfl_down_sync(0xFFFFFFFFu, J, off);

        if (lane == 0) {
            lossc[c] = (J + 0.5f) * (1.0f / (float)NB);
            gtsc[c]  = gts;
        }
    }
    __syncthreads();

    if (tid == 0) {
        float s = 0.f; int np = 0;
#pragma unroll
        for (int k = 0; k < CNUM; k++) {
            if (gtsc[k] > 0u) { s += lossc[k]; np++; }
        }
        out[0] = s / (float)(np > 0 ? np : 1);
    }
}

// ---------------------------------------------------------------------------
extern "C" void kernel_launch(void* const* d_in, const int* in_sizes, int n_in,
                              void* d_out, int out_size)
{
    const float* logits = (const float*)d_in[0];
    const int*   gt     = (const int*)d_in[1];
    float*       out    = (float*)d_out;

    lovasz_kernel<<<GRID, 256>>>(logits, gt, out);
}

// round 15
// speedup vs baseline: 1.0920x; 1.0920x over previous
#include <cuda_runtime.h>
#include <cuda_fp16.h>

// Problem constants
#define CNUM  19
#define NPAIR 10            // class pairs per pixel (pair 9 = {18, dummy})
#define NB    32            // error bins over [0,1]
#define STRIDE 80           // words/class: nonfg bin b at [b] (b<=32); fg bin b at [40+b]
#define NREP  16            // histogram replicas
#define HW    262144        // 512*512
#define PTOT  1048576       // 4*512*512
#define GRID  (PTOT / 256)  // 4096 blocks, 256 threads, 1 pixel/thread

// [replica][class][80]; zero-init at load; fused epilogue re-zeroes.
__device__ __align__(16) unsigned g_hist[NREP * CNUM * STRIDE];
__device__ unsigned g_done;          // completion counter (wraps to 0 each run)

__device__ __forceinline__ float rcpf(float x) { float r; asm("rcp.approx.ftz.f32 %0,%1;":"=f"(r):"f"(x)); return r; }

// ---------------------------------------------------------------------------
// Fused kernel: 1 pixel/thread softmax + warp-aggregated error histogram
// (R13 mainloop, 31 regs / high occupancy); last block to finish merges the
// 16 replicas and computes the loss in-kernel (R14 epilogue).
// ---------------------------------------------------------------------------
__global__ void __launch_bounds__(256) lovasz_kernel(
    const float* __restrict__ logits, const int* __restrict__ gt,
    float* __restrict__ out)
{
    const int tid  = threadIdx.x;
    const int lane = tid & 31;
    const int wid  = tid >> 5;

    // ---------------- histogram phase (identical math to R13) ----------------
    int p  = blockIdx.x * blockDim.x + tid;
    int b  = p >> 18;
    int hw = p & (HW - 1);
    const float* base = logits + (size_t)b * CNUM * HW + hw;

    int lab = gt[p];
    bool valid = ((unsigned)lab < (unsigned)CNUM);
    int labx = valid ? lab : -1;

    const __half2 L2E2 = __float2half2_rn(1.4426950408889634f);

    __half2 e2[NPAIR];
    float S = 0.f;
#pragma unroll
    for (int j = 0; j < NPAIR; j++) {
        float xa = __ldg(base + (size_t)(2 * j) * HW);
        float xb = (j < 9) ? __ldg(base + (size_t)(2 * j + 1) * HW)
                           : -1.0e4f;        // dummy: exp->0
        __half2 y = __hmul2(__floats2half2_rn(xa, xb), L2E2);
        __half2 ee = h2exp2(y);
        e2[j] = ee;
        float2 ef = __half22float2(ee);
        S += ef.x + ef.y;
    }

    float rsn = rcpf(S) * (float)NB;         // NB / S

    unsigned* baseH = g_hist + (size_t)(blockIdx.x & (NREP - 1)) * (CNUM * STRIDE);

#pragma unroll
    for (int j = 0; j < NPAIR; j++) {
        float2 ef = __half22float2(e2[j]);
#pragma unroll
        for (int h = 0; h < 2; h++) {
            int c = 2 * j + h;
            if (c >= CNUM) break;            // compile-time (j==9,h==1)
            float pcN = (h ? ef.y : ef.x) * rsn;
            unsigned idx;
            if (c == labx) {
                int ig = (int)((float)NB - pcN);
                ig = ig < 0 ? 0 : ig;
                idx = 40u + (unsigned)ig;                // [40,72] (never 0)
            } else {
                idx = (unsigned)pcN;                     // [0,32]
            }
            bool emit = valid && (idx != 0u);            // bin-0 nonfg: dead
            unsigned off = emit ? ((unsigned)c * STRIDE + idx)
                                : (0x40000000u + (unsigned)c);
            unsigned mask = __match_any_sync(0xFFFFFFFFu, off);
            bool leader = ((unsigned)lane == (unsigned)(__ffs(mask) - 1));
            if (emit && leader)
                atomicAdd(baseH + off, __popc(mask));
        }
    }

    // ---------------- completion detection ----------------
    __shared__ bool amLast;
    __syncthreads();
    if (tid == 0) {
        __threadfence();
        unsigned prev = atomicInc(&g_done, GRID - 1);   // wraps to 0 at GRID
        amLast = (prev == GRID - 1);
    }
    __syncthreads();
    if (!amLast) return;

    // ---------------- fused epilogue (last block only) ----------------
    __threadfence();

    __shared__ unsigned mg[CNUM * STRIDE];          // 1520 words
    __shared__ float    lossc[CNUM];
    __shared__ unsigned gtsc[CNUM];

    for (int i = tid; i < CNUM * STRIDE; i += 256) {
        unsigned sum = 0;
#pragma unroll
        for (int r = 0; r < NREP; r++) {
            size_t idx = (size_t)r * (CNUM * STRIDE) + i;
            sum += g_hist[idx];
            g_hist[idx] = 0u;                       // restore zero-invariant
        }
        mg[i] = sum;
    }
    __syncthreads();

    // one warp per class (8 warps cover 19 classes in 3 rounds)
    for (int c = wid; c < CNUM; c += 8) {
        const unsigned* row = mg + c * STRIDE;
        unsigned u = row[lane];                     // nonfg err bin t=lane
        unsigned f = row[40 + lane];                // fg err bin t=lane
        unsigned u32 = row[32];
        unsigned f32 = row[72];

        // inclusive suffix scan over lanes (t = lane .. 31)
#pragma unroll
        for (int off = 1; off < 32; off <<= 1) {
            unsigned un = __shfl_down_sync(0xFFFFFFFFu, u, off);
            unsigned fn = __shfl_down_sync(0xFFFFFFFFu, f, off);
            if (lane + off < 32) { u += un; f += fn; }
        }
        u += u32; f += f32;                         // include bin 32

        unsigned gts = __shfl_sync(0xFFFFFFFFu, f, 0);

        float J = 0.f;
        if (lane >= 1 && gts > 0)
            J = 1.f - __fdividef((float)(gts - f), (float)(gts + u));
#pragma unroll
        for (int off = 16; off > 0; off >>= 1)
            J += __shfl_down_sync(0xFFFFFFFFu, J, off);

        if (lane == 0) {
            lossc[c] = (J + 0.5f) * (1.0f / (float)NB);
            gtsc[c]  = gts;
        }
    }
    __syncthreads();

    if (tid == 0) {
        float s = 0.f; int np = 0;
#pragma unroll
        for (int k = 0; k < CNUM; k++) {
            if (gtsc[k] > 0u) { s += lossc[k]; np++; }
        }
        out[0] = s / (float)(np > 0 ? np : 1);
    }
}

// ---------------------------------------------------------------------------
extern "C" void kernel_launch(void* const* d_in, const int* in_sizes, int n_in,
                              void* d_out, int out_size)
{
    const float* logits = (const float*)d_in[0];
    const int*   gt     = (const int*)d_in[1];
    float*       out    = (float*)d_out;

    lovasz_kernel<<<GRID, 256>>>(logits, gt, out);
}

// round 16
// speedup vs baseline: 1.0952x; 1.0029x over previous
#include <cuda_runtime.h>
#include <cuda_fp16.h>

// Problem constants
#define CNUM  19
#define NPAIR 10            // class pairs per pixel (pair 9 = {18, dummy})
#define NB    32            // error bins over [0,1]
#define STRIDE 80           // words/class: nonfg bin b at [b] (b<=32); fg bin b at [40+b]
#define NREP  16            // histogram replicas
#define HW    262144        // 512*512
#define PTOT  1048576       // 4*512*512

// [replica][class][80]; zero-init at load; loss_kernel re-zeroes.
__device__ __align__(16) unsigned g_hist[NREP * CNUM * STRIDE];
__device__ float    g_lossc[CNUM];
__device__ unsigned g_gts[CNUM];
__device__ unsigned g_done;          // completion counter (wraps to 0 each run)

__device__ __forceinline__ float rcpf(float x) { float r; asm("rcp.approx.ftz.f32 %0,%1;":"=f"(r):"f"(x)); return r; }

// ---------------------------------------------------------------------------
// Pass 1: f16x2 exps, fp32 binning, warp-aggregated REDs.
// Scatter loop thinned: class is warp-uniform per iteration, so MATCH keys on
// the bin index alone (0 = dead/non-emitting); fg bin precomputed once.
// ---------------------------------------------------------------------------
__global__ void __launch_bounds__(256) hist_kernel(
    const float* __restrict__ logits, const int* __restrict__ gt)
{
    int p = blockIdx.x * blockDim.x + threadIdx.x;   // grid exact: no tail
    int lane = threadIdx.x & 31;

    int b  = p >> 18;
    int hw = p & (HW - 1);
    const float* base = logits + (size_t)b * CNUM * HW + hw;

    int lab = gt[p];
    bool valid = ((unsigned)lab < (unsigned)CNUM);
    int labx = valid ? lab : -1;

    const __half2 L2E2 = __float2half2_rn(1.4426950408889634f);

    __half2 e2[NPAIR];
    float S = 0.f;
    float elab = 0.f;                        // e value of the label class
#pragma unroll
    for (int j = 0; j < NPAIR; j++) {
        float xa = __ldg(base + (size_t)(2 * j) * HW);
        float xb = (j < 9) ? __ldg(base + (size_t)(2 * j + 1) * HW)
                           : -1.0e4f;        // dummy: exp->0
        __half2 y = __hmul2(__floats2half2_rn(xa, xb), L2E2);
        __half2 ee = h2exp2(y);
        e2[j] = ee;
        float2 ef = __half22float2(ee);
        S += ef.x + ef.y;
        elab = (2 * j     == labx) ? ef.x : elab;   // bit-identical extraction
        elab = (2 * j + 1 == labx) ? ef.y : elab;
    }

    float rsn = rcpf(S) * (float)NB;         // NB / S

    // fg bin for the label class (same FMUL/F2I rounding as the old in-loop path)
    float pcl = elab * rsn;
    int ig = (int)((float)NB - pcl);
    ig = ig < 0 ? 0 : ig;
    unsigned fgi = 40u + (unsigned)ig;       // in [40,72], never 0

    unsigned* baseH = g_hist + (size_t)(blockIdx.x & (NREP - 1)) * (CNUM * STRIDE);

#pragma unroll
    for (int j = 0; j < NPAIR; j++) {
        float2 ef = __half22float2(e2[j]);
#pragma unroll
        for (int h = 0; h < 2; h++) {
            int c = 2 * j + h;
            if (c >= CNUM) break;            // compile-time (j==9,h==1)
            float pcN = (h ? ef.y : ef.x) * rsn;
            unsigned idx = (unsigned)pcN;                // [0,32]; 0 = dead bin
            idx = (c == labx) ? fgi : idx;               // label class -> fg bin
            unsigned key = valid ? idx : 0u;             // 0 = non-emitting
            unsigned mask = __match_any_sync(0xFFFFFFFFu, key);
            bool leader = ((unsigned)lane == (unsigned)(__ffs(mask) - 1));
            if ((key != 0u) && leader)
                atomicAdd(baseH + (unsigned)c * STRIDE + key, __popc(mask));
        }
    }
}

// ---------------------------------------------------------------------------
// Pass 2 (+fused finalize): one block per class, 128 threads (R13, proven).
// ---------------------------------------------------------------------------
__global__ void __launch_bounds__(128) loss_kernel(float* __restrict__ out) {
    const int c = blockIdx.x;
    const int t = threadIdx.x;

    __shared__ unsigned mg[STRIDE];
    __shared__ unsigned sU[33], sF[33];
    __shared__ float    red[32];
    __shared__ bool     amLast;

    if (t < STRIDE) {
        unsigned* cls = g_hist + (size_t)c * STRIDE;
        unsigned sum = 0;
#pragma unroll
        for (int r = 0; r < NREP; r++) {
            size_t idx = (size_t)r * (CNUM * STRIDE) + t;
            sum += cls[idx];
            cls[idx] = 0u;                    // restore zero-invariant
        }
        mg[t] = sum;
    }
    __syncthreads();

    if (t <= 32) {
        sU[t] = mg[t];                        // nonfg err bin t (bin 0 unused)
        sF[t] = mg[40 + t];                   // fg err bin t
    }
    __syncthreads();

    for (int off = 1; off < 33; off <<= 1) {
        unsigned u = 0, f = 0;
        if (t <= 32) {
            u = sU[t]; f = sF[t];
            if (t + off <= 32) { u += sU[t + off]; f += sF[t + off]; }
        }
        __syncthreads();
        if (t <= 32) { sU[t] = u; sF[t] = f; }
        __syncthreads();
    }

    unsigned gts = sF[0];
    float J = 0.f;
    if (t >= 1 && t < NB && gts > 0)
        J = 1.f - __fdividef((float)(gts - sF[t]), (float)(gts + sU[t]));
    if (t < 32) red[t] = J;
    __syncthreads();

    for (int off = 16; off > 0; off >>= 1) {
        if (t < off) red[t] += red[t + off];
        __syncthreads();
    }

    if (t == 0) {
        g_lossc[c] = (red[0] + 0.5f) * (1.0f / (float)NB);
        g_gts[c]   = gts;
        __threadfence();
        unsigned prev = atomicInc(&g_done, CNUM - 1);   // wraps to 0 at CNUM
        amLast = (prev == CNUM - 1);
    }
    __syncthreads();

    if (amLast && t == 0) {
        __threadfence();
        float s = 0.f; int np = 0;
#pragma unroll
        for (int k = 0; k < CNUM; k++) {
            if (g_gts[k] > 0u) { s += g_lossc[k]; np++; }
        }
        out[0] = s / (float)(np > 0 ? np : 1);
    }
}

// ---------------------------------------------------------------------------
extern "C" void kernel_launch(void* const* d_in, const int* in_sizes, int n_in,
                              void* d_out, int out_size)
{
    const float* logits = (const float*)d_in[0];
    const int*   gt     = (const int*)d_in[1];
    float*       out    = (float*)d_out;

    hist_kernel<<<PTOT / 256, 256>>>(logits, gt);
    loss_kernel<<<CNUM, 128>>>(out);
}